// round 11
// baseline (speedup 1.0000x reference)
#include <cuda_runtime.h>
#include <cuda_fp16.h>
#include <cstdint>

#define NB 32
#define NS 8192
#define ND 64
#define BK 32                // seq rows per smem stage
#define NUNITS (NS / BK)     // 256 stage units per batch
#define NCTA 592             // = 4 * 148: one perfectly balanced wave
#define KP 16                // half2 k-pair rows per stage
#define DP2 72               // words per kpair row (64 + 8 pad): CF frag LDS
#define MATW (KP * DP2)      // 1152 words per matrix per buffer

// Partial results: [NCTA][2][64][64]  (mat0 = rr+ii, mat1 = ri - ri^T)
__device__ __align__(16) float g_scratch[NCTA * 2 * ND * ND];

// Pack two floats into f16x2: lo -> low half (smaller k), hi -> high half.
__device__ __forceinline__ unsigned pk(float lo, float hi) {
    unsigned u;
    asm("cvt.rn.f16x2.f32 %0, %1, %2;" : "=r"(u) : "f"(hi), "f"(lo));
    return u;
}

// NOT volatile: ptxas may interleave/schedule MMAs. K=16 per instruction.
__device__ __forceinline__ void mma_f16(float c[4],
                                        unsigned a0, unsigned a1, unsigned a2, unsigned a3,
                                        unsigned b0, unsigned b1) {
    asm("mma.sync.aligned.m16n8k16.row.col.f32.f16.f16.f32 "
        "{%0,%1,%2,%3}, {%4,%5,%6,%7}, {%8,%9}, {%0,%1,%2,%3};"
        : "+f"(c[0]), "+f"(c[1]), "+f"(c[2]), "+f"(c[3])
        : "r"(a0), "r"(a1), "r"(a2), "r"(a3), "r"(b0), "r"(b1));
}

__global__ __launch_bounds__(128, 4) void gram_kernel(const float* __restrict__ gr,
                                                      const float* __restrict__ gi) {
    // Main loop: [2 buf][2 mat][KP][DP2] u32 = 4608 words (18.4 KB).
    // Epilogue reuses as sA[64][65] + sM[64][65] = 8320 floats.
    __shared__ __align__(16) float s_raw[8320];
    unsigned* const sw = (unsigned*)s_raw;

    const int cid = blockIdx.x;
    // Batch / chunk mapping: batches 0-15 have 19 chunks, 16-31 have 18.
    int b, j, nc;
    if (cid < 304) { b = cid / 19;        j = cid % 19;        nc = 19; }
    else           { b = 16 + (cid - 304) / 18; j = (cid - 304) % 18; nc = 18; }
    // Distribute 256 stage-units over nc chunks.
    const int qb  = NUNITS / nc;                 // 13 or 14
    const int rm  = NUNITS - qb * nc;            // 9 or 4
    const int nst = qb + (j < rm ? 1 : 0);
    const int st0 = j * qb + (j < rm ? j : rm);

    const int tid  = threadIdx.x;
    const int L    = tid & 31;
    const int warp = tid >> 5;                  // 0..3
    const int g    = L >> 2;
    const int t    = L & 3;
    const int m0w  = (warp & 1) * 32;           // warp's 32-row m block
    const int n0w  = (warp >> 1) * 32;          // warp's 32-col n block

    const float* baseR = gr + ((long)b * NS + (long)st0 * BK) * ND;
    const float* baseI = gi + ((long)b * NS + (long)st0 * BK) * ND;

    float accR[2][4][4];  // rr + ii
    float accM[2][4][4];  // ri
#pragma unroll
    for (int bd = 0; bd < 2; bd++)
#pragma unroll
        for (int jj = 0; jj < 4; jj++)
#pragma unroll
            for (int c = 0; c < 4; c++) { accR[bd][jj][c] = 0.f; accM[bd][jj][c] = 0.f; }

    // Producer unit u = tid + h*128: kpair p = u>>4 (0..15), d-quad q = u&15.
    float4 rv0, rv1, iv0, iv1;

#define LOADC(st_, h_) do {                                                    \
        const int u_ = tid + (h_) * 128;                                       \
        const int p_ = u_ >> 4, q_ = u_ & 15;                                  \
        const long oA_ = ((long)(st_) * BK + 2 * p_) * ND + 4 * q_;            \
        rv0 = *(const float4*)(baseR + oA_);                                   \
        rv1 = *(const float4*)(baseR + oA_ + ND);                              \
        iv0 = *(const float4*)(baseI + oA_);                                   \
        iv1 = *(const float4*)(baseI + oA_ + ND);                              \
    } while (0)

#define STSC(buf_, h_) do {                                                    \
        const int u_ = tid + (h_) * 128;                                       \
        const int p_ = u_ >> 4, q_ = u_ & 15;                                  \
        unsigned* bp_ = sw + (buf_) * 2 * MATW + p_ * DP2 + 4 * q_;            \
        *(uint4*)bp_ = make_uint4(pk(rv0.x, rv1.x), pk(rv0.y, rv1.y),          \
                                  pk(rv0.z, rv1.z), pk(rv0.w, rv1.w));         \
        *(uint4*)(bp_ + MATW) = make_uint4(pk(iv0.x, iv1.x), pk(iv0.y, iv1.y), \
                                           pk(iv0.z, iv1.z), pk(iv0.w, iv1.w)); \
    } while (0)

#define COMP(cR_, cI_, s_) do {                                                \
        const int kb_ = 8 * (s_);                                              \
        const unsigned* pr0_ = (cR_) + (kb_ + t) * DP2;                        \
        const unsigned* pr1_ = (cR_) + (kb_ + t + 4) * DP2;                    \
        const unsigned* pi0_ = (cI_) + (kb_ + t) * DP2;                        \
        const unsigned* pi1_ = (cI_) + (kb_ + t + 4) * DP2;                    \
        unsigned aR_[2][4], aI_[2][4];                                         \
        _Pragma("unroll")                                                      \
        for (int bd_ = 0; bd_ < 2; bd_++) {                                    \
            const int m_ = m0w + 16 * bd_ + g;                                 \
            aR_[bd_][0] = pr0_[m_];  aR_[bd_][1] = pr0_[m_ + 8];               \
            aR_[bd_][2] = pr1_[m_];  aR_[bd_][3] = pr1_[m_ + 8];               \
            aI_[bd_][0] = pi0_[m_];  aI_[bd_][1] = pi0_[m_ + 8];               \
            aI_[bd_][2] = pi1_[m_];  aI_[bd_][3] = pi1_[m_ + 8];               \
        }                                                                      \
        unsigned br0_[4], br1_[4], bi0_[4], bi1_[4];                           \
        _Pragma("unroll")                                                      \
        for (int j_ = 0; j_ < 4; j_++) {                                       \
            const int n_ = n0w + j_ * 8 + g;                                   \
            br0_[j_] = pr0_[n_];  br1_[j_] = pr1_[n_];                         \
            bi0_[j_] = pi0_[n_];  bi1_[j_] = pi1_[n_];                         \
        }                                                                      \
        _Pragma("unroll")                                                      \
        for (int bd_ = 0; bd_ < 2; bd_++)                                      \
            _Pragma("unroll")                                                  \
            for (int j_ = 0; j_ < 4; j_++) {                                   \
                mma_f16(accR[bd_][j_], aR_[bd_][0], aR_[bd_][1],               \
                        aR_[bd_][2], aR_[bd_][3], br0_[j_], br1_[j_]);         \
                mma_f16(accM[bd_][j_], aR_[bd_][0], aR_[bd_][1],               \
                        aR_[bd_][2], aR_[bd_][3], bi0_[j_], bi1_[j_]);         \
            }                                                                  \
        _Pragma("unroll")                                                      \
        for (int bd_ = 0; bd_ < 2; bd_++)                                      \
            _Pragma("unroll")                                                  \
            for (int j_ = 0; j_ < 4; j_++)                                     \
                mma_f16(accR[bd_][j_], aI_[bd_][0], aI_[bd_][1],               \
                        aI_[bd_][2], aI_[bd_][3], bi0_[j_], bi1_[j_]);         \
    } while (0)

    // ---- prologue: stage 0 into buffer 0 ----
    LOADC(0, 0); STSC(0, 0);
    LOADC(0, 1); STSC(0, 1);
    __syncthreads();

#pragma unroll 1
    for (int st = 0; st < nst; st++) {
        const int cur = st & 1;
        const int nxt = cur ^ 1;
        const bool more = (st + 1 < nst);
        const unsigned* cR = sw + cur * 2 * MATW;
        const unsigned* cI = cR + MATW;

        if (more) LOADC(st + 1, 0);
        COMP(cR, cI, 0);
        if (more) { STSC(nxt, 0); LOADC(st + 1, 1); }
        COMP(cR, cI, 1);
        if (more) STSC(nxt, 1);
        __syncthreads();
    }

    // ---- epilogue: stage through smem, write 2 partial matrices ----
    // C frag map: c0:(r,2t) c1:(r,2t+1) c2:(r+8,2t) c3:(r+8,2t+1)
    float* const sA = s_raw;             // [64][65] rr+ii
    float* const sM = s_raw + ND * 65;   // [64][65] ri
#pragma unroll
    for (int bd = 0; bd < 2; bd++)
#pragma unroll
        for (int jj = 0; jj < 4; jj++) {
            const int r0 = m0w + bd * 16 + g;
            const int r1 = r0 + 8;
            const int n  = n0w + jj * 8 + 2 * t;
            sA[r0 * 65 + n]     = accR[bd][jj][0];
            sA[r0 * 65 + n + 1] = accR[bd][jj][1];
            sA[r1 * 65 + n]     = accR[bd][jj][2];
            sA[r1 * 65 + n + 1] = accR[bd][jj][3];
            sM[r0 * 65 + n]     = accM[bd][jj][0];
            sM[r0 * 65 + n + 1] = accM[bd][jj][1];
            sM[r1 * 65 + n]     = accM[bd][jj][2];
            sM[r1 * 65 + n + 1] = accM[bd][jj][3];
        }
    __syncthreads();

    float* const base = g_scratch + ((long)cid * 2 << 12);
#pragma unroll
    for (int it = 0; it < 8; it++) {
        const int idx = it * 128 + tid;    // 0..1023
        const int row = idx >> 4;
        const int col = (idx & 15) * 4;
        float4 v0, v1;
        v0.x = sA[row * 65 + col];     v0.y = sA[row * 65 + col + 1];
        v0.z = sA[row * 65 + col + 2]; v0.w = sA[row * 65 + col + 3];
        // Antisymmetrized here: mat1 = ri - ri^T (exact 0 diagonal).
        v1.x = sM[row * 65 + col]     - sM[(col    ) * 65 + row];
        v1.y = sM[row * 65 + col + 1] - sM[(col + 1) * 65 + row];
        v1.z = sM[row * 65 + col + 2] - sM[(col + 2) * 65 + row];
        v1.w = sM[row * 65 + col + 3] - sM[(col + 3) * 65 + row];
        *(float4*)(base +        row * ND + col) = v0;   // mat0 = rr+ii
        *(float4*)(base + 4096 + row * ND + col) = v1;   // mat1 = ri - ri^T
    }
}

__global__ __launch_bounds__(256) void reduce_kernel(float* __restrict__ out) {
    // One float per thread: 262144 threads. m is block-uniform (4096-float regions).
    const int f   = blockIdx.x * blockDim.x + threadIdx.x;
    const int b   = f >> 13;        // 8192 floats per batch (2 output mats)
    const int rem = f & 8191;
    const int m   = rem >> 12;      // 0 = real, 1 = imag (uniform per block)
    const int ij  = rem & 4095;

    int cb, nc;
    if (b < 16) { cb = b * 19;              nc = 19; }
    else        { cb = 304 + (b - 16) * 18; nc = 18; }

    const float inv = 1.0f / (float)NS;
    const float* p = g_scratch + (((long)(cb * 2 + m)) << 12) + ij;
    float a = 0.f;
#pragma unroll 19
    for (int j = 0; j < nc; j++)
        a += p[(long)j * 8192];
    out[(long)m * (NB * ND * ND) + b * (ND * ND) + ij] = a * inv;
}

extern "C" void kernel_launch(void* const* d_in, const int* in_sizes, int n_in,
                              void* d_out, int out_size) {
    const float* input_real = (const float*)d_in[0];
    const float* input_imag = (const float*)d_in[1];
    float* out = (float*)d_out;

    gram_kernel<<<NCTA, 128>>>(input_real, input_imag);
    reduce_kernel<<<1024, 256>>>(out);

    (void)in_sizes; (void)n_in; (void)out_size;
}

// round 12
// speedup vs baseline: 1.1937x; 1.1937x over previous
#include <cuda_runtime.h>
#include <cuda_fp16.h>
#include <cstdint>

#define NB 32
#define NS 8192
#define ND 64
#define NSPLIT 16
#define ROWS (NS / NSPLIT)   // 512 seq rows per CTA
#define BK 32                // seq rows per smem stage
#define NSTAGE (ROWS / BK)   // 16
#define KP 16                // half2 k-pair rows per stage
#define DP2 72               // words per kpair row (64 + 8 pad): CF frag LDS
#define MATW (KP * DP2)      // 1152 words per matrix per buffer

// Partial results: [NSPLIT][NB][2][64][64]  (mat0 = rr+ii, mat1 = ri - ri^T)
__device__ __align__(16) float g_scratch[NSPLIT * NB * 2 * ND * ND];

// Pack two floats into f16x2: lo -> low half (smaller k), hi -> high half.
__device__ __forceinline__ unsigned pk(float lo, float hi) {
    unsigned u;
    asm("cvt.rn.f16x2.f32 %0, %1, %2;" : "=r"(u) : "f"(hi), "f"(lo));
    return u;
}

// NOT volatile: ptxas may interleave/schedule MMAs. K=16 per instruction.
__device__ __forceinline__ void mma_f16(float c[4],
                                        unsigned a0, unsigned a1, unsigned a2, unsigned a3,
                                        unsigned b0, unsigned b1) {
    asm("mma.sync.aligned.m16n8k16.row.col.f32.f16.f16.f32 "
        "{%0,%1,%2,%3}, {%4,%5,%6,%7}, {%8,%9}, {%0,%1,%2,%3};"
        : "+f"(c[0]), "+f"(c[1]), "+f"(c[2]), "+f"(c[3])
        : "r"(a0), "r"(a1), "r"(a2), "r"(a3), "r"(b0), "r"(b1));
}

__global__ __launch_bounds__(128, 4) void gram_kernel(const float* __restrict__ gr,
                                                      const float* __restrict__ gi) {
    // Main loop: [2 buf][2 mat][KP][DP2] u32 = 4608 words (18.4 KB).
    // Epilogue reuses as sA[64][65] + sM[64][65] = 8320 floats.
    __shared__ __align__(16) float s_raw[8320];
    unsigned* const sw = (unsigned*)s_raw;

    const int b    = blockIdx.x >> 4;           // NSPLIT = 16
    const int sp   = blockIdx.x & (NSPLIT - 1);
    const int tid  = threadIdx.x;
    const int L    = tid & 31;
    const int warp = tid >> 5;                  // 0..3
    const int g    = L >> 2;
    const int t    = L & 3;
    const int m0w  = (warp & 1) * 32;           // warp's 32-row m block
    const int n0w  = (warp >> 1) * 32;          // warp's 32-col n block

    const float* baseR = gr + ((long)b * NS + (long)sp * ROWS) * ND;
    const float* baseI = gi + ((long)b * NS + (long)sp * ROWS) * ND;

    float accR[2][4][4];  // rr + ii
    float accM[2][4][4];  // ri
#pragma unroll
    for (int bd = 0; bd < 2; bd++)
#pragma unroll
        for (int jj = 0; jj < 4; jj++)
#pragma unroll
            for (int c = 0; c < 4; c++) { accR[bd][jj][c] = 0.f; accM[bd][jj][c] = 0.f; }

    // Producer unit u = tid + h*128: kpair p = u>>4 (0..15), d-quad q = u&15.
    float4 rv0, rv1, iv0, iv1;

#define LOADC(st_, h_) do {                                                    \
        const int u_ = tid + (h_) * 128;                                       \
        const int p_ = u_ >> 4, q_ = u_ & 15;                                  \
        const long oA_ = ((long)(st_) * BK + 2 * p_) * ND + 4 * q_;            \
        rv0 = *(const float4*)(baseR + oA_);                                   \
        rv1 = *(const float4*)(baseR + oA_ + ND);                              \
        iv0 = *(const float4*)(baseI + oA_);                                   \
        iv1 = *(const float4*)(baseI + oA_ + ND);                              \
    } while (0)

#define STSC(buf_, h_) do {                                                    \
        const int u_ = tid + (h_) * 128;                                       \
        const int p_ = u_ >> 4, q_ = u_ & 15;                                  \
        unsigned* bp_ = sw + (buf_) * 2 * MATW + p_ * DP2 + 4 * q_;            \
        *(uint4*)bp_ = make_uint4(pk(rv0.x, rv1.x), pk(rv0.y, rv1.y),          \
                                  pk(rv0.z, rv1.z), pk(rv0.w, rv1.w));         \
        *(uint4*)(bp_ + MATW) = make_uint4(pk(iv0.x, iv1.x), pk(iv0.y, iv1.y), \
                                           pk(iv0.z, iv1.z), pk(iv0.w, iv1.w)); \
    } while (0)

#define COMP(cR_, cI_, s_) do {                                                \
        const int kb_ = 8 * (s_);                                              \
        const unsigned* pr0_ = (cR_) + (kb_ + t) * DP2;                        \
        const unsigned* pr1_ = (cR_) + (kb_ + t + 4) * DP2;                    \
        const unsigned* pi0_ = (cI_) + (kb_ + t) * DP2;                        \
        const unsigned* pi1_ = (cI_) + (kb_ + t + 4) * DP2;                    \
        unsigned aR_[2][4], aI_[2][4];                                         \
        _Pragma("unroll")                                                      \
        for (int bd_ = 0; bd_ < 2; bd_++) {                                    \
            const int m_ = m0w + 16 * bd_ + g;                                 \
            aR_[bd_][0] = pr0_[m_];  aR_[bd_][1] = pr0_[m_ + 8];               \
            aR_[bd_][2] = pr1_[m_];  aR_[bd_][3] = pr1_[m_ + 8];               \
            aI_[bd_][0] = pi0_[m_];  aI_[bd_][1] = pi0_[m_ + 8];               \
            aI_[bd_][2] = pi1_[m_];  aI_[bd_][3] = pi1_[m_ + 8];               \
        }                                                                      \
        unsigned br0_[4], br1_[4], bi0_[4], bi1_[4];                           \
        _Pragma("unroll")                                                      \
        for (int j_ = 0; j_ < 4; j_++) {                                       \
            const int n_ = n0w + j_ * 8 + g;                                   \
            br0_[j_] = pr0_[n_];  br1_[j_] = pr1_[n_];                         \
            bi0_[j_] = pi0_[n_];  bi1_[j_] = pi1_[n_];                         \
        }                                                                      \
        _Pragma("unroll")                                                      \
        for (int bd_ = 0; bd_ < 2; bd_++)                                      \
            _Pragma("unroll")                                                  \
            for (int j_ = 0; j_ < 4; j_++) {                                   \
                mma_f16(accR[bd_][j_], aR_[bd_][0], aR_[bd_][1],               \
                        aR_[bd_][2], aR_[bd_][3], br0_[j_], br1_[j_]);         \
                mma_f16(accM[bd_][j_], aR_[bd_][0], aR_[bd_][1],               \
                        aR_[bd_][2], aR_[bd_][3], bi0_[j_], bi1_[j_]);         \
            }                                                                  \
        _Pragma("unroll")                                                      \
        for (int bd_ = 0; bd_ < 2; bd_++)                                      \
            _Pragma("unroll")                                                  \
            for (int j_ = 0; j_ < 4; j_++)                                     \
                mma_f16(accR[bd_][j_], aI_[bd_][0], aI_[bd_][1],               \
                        aI_[bd_][2], aI_[bd_][3], bi0_[j_], bi1_[j_]);         \
    } while (0)

    // ---- prologue: stage 0 into buffer 0 ----
    LOADC(0, 0); STSC(0, 0);
    LOADC(0, 1); STSC(0, 1);
    __syncthreads();

#pragma unroll 1
    for (int st = 0; st < NSTAGE; st++) {
        const int cur = st & 1;
        const int nxt = cur ^ 1;
        const bool more = (st + 1 < NSTAGE);
        const unsigned* cR = sw + cur * 2 * MATW;
        const unsigned* cI = cR + MATW;

        if (more) LOADC(st + 1, 0);
        COMP(cR, cI, 0);
        if (more) { STSC(nxt, 0); LOADC(st + 1, 1); }
        COMP(cR, cI, 1);
        if (more) STSC(nxt, 1);
        __syncthreads();
    }

    // ---- epilogue: stage through smem, write 2 partial matrices ----
    // C frag map: c0:(r,2t) c1:(r,2t+1) c2:(r+8,2t) c3:(r+8,2t+1)
    float* const sA = s_raw;             // [64][65] rr+ii
    float* const sM = s_raw + ND * 65;   // [64][65] ri
#pragma unroll
    for (int bd = 0; bd < 2; bd++)
#pragma unroll
        for (int jj = 0; jj < 4; jj++) {
            const int r0 = m0w + bd * 16 + g;
            const int r1 = r0 + 8;
            const int n  = n0w + jj * 8 + 2 * t;
            sA[r0 * 65 + n]     = accR[bd][jj][0];
            sA[r0 * 65 + n + 1] = accR[bd][jj][1];
            sA[r1 * 65 + n]     = accR[bd][jj][2];
            sA[r1 * 65 + n + 1] = accR[bd][jj][3];
            sM[r0 * 65 + n]     = accM[bd][jj][0];
            sM[r0 * 65 + n + 1] = accM[bd][jj][1];
            sM[r1 * 65 + n]     = accM[bd][jj][2];
            sM[r1 * 65 + n + 1] = accM[bd][jj][3];
        }
    __syncthreads();

    float* const base = g_scratch + ((long)(sp * NB + b) * 2 << 12);
#pragma unroll
    for (int it = 0; it < 8; it++) {
        const int idx = it * 128 + tid;    // 0..1023
        const int row = idx >> 4;
        const int col = (idx & 15) * 4;
        float4 v0, v1;
        v0.x = sA[row * 65 + col];     v0.y = sA[row * 65 + col + 1];
        v0.z = sA[row * 65 + col + 2]; v0.w = sA[row * 65 + col + 3];
        // Antisymmetrized here: mat1 = ri - ri^T (exact 0 diagonal).
        v1.x = sM[row * 65 + col]     - sM[(col    ) * 65 + row];
        v1.y = sM[row * 65 + col + 1] - sM[(col + 1) * 65 + row];
        v1.z = sM[row * 65 + col + 2] - sM[(col + 2) * 65 + row];
        v1.w = sM[row * 65 + col + 3] - sM[(col + 3) * 65 + row];
        *(float4*)(base +        row * ND + col) = v0;   // mat0 = rr+ii
        *(float4*)(base + 4096 + row * ND + col) = v1;   // mat1 = ri - ri^T
    }
}

__global__ __launch_bounds__(256) void reduce_kernel(float* __restrict__ out) {
    // One float per thread: 262144 threads. Branch-free: real and imag paths
    // are the same single-stream sum over NSPLIT fixed iterations.
    const int f   = blockIdx.x * blockDim.x + threadIdx.x;
    const int b   = f >> 13;        // 8192 floats per batch (2 output mats)
    const int rem = f & 8191;
    const int m   = rem >> 12;      // 0 = real, 1 = imag (uniform per block)
    const int ij  = rem & 4095;

    const float* p = g_scratch + (((long)(b * 2 + m)) << 12) + ij;
    float a = 0.f;
#pragma unroll
    for (int sp = 0; sp < NSPLIT; sp++)
        a += p[(long)sp * (NB * 2 * 4096)];
    out[(long)m * (NB * ND * ND) + b * (ND * ND) + ij] = a * (1.0f / (float)NS);
}

extern "C" void kernel_launch(void* const* d_in, const int* in_sizes, int n_in,
                              void* d_out, int out_size) {
    const float* input_real = (const float*)d_in[0];
    const float* input_imag = (const float*)d_in[1];
    float* out = (float*)d_out;

    gram_kernel<<<NB * NSPLIT, 128>>>(input_real, input_imag);
    reduce_kernel<<<1024, 256>>>(out);

    (void)in_sizes; (void)n_in; (void)out_size;
}